// round 6
// baseline (speedup 1.0000x reference)
#include <cuda_runtime.h>
#include <math.h>
#include <stdint.h>

#define Bsz 256
#define Tsz 512
#define Dsz 256
#define Ksz 256

__device__ float g_xU[Bsz * Tsz * Ksz];   // 128 MB scratch for xU = x@U + b

// ===========================================================================
// Helpers
// ===========================================================================
__device__ __forceinline__ unsigned long long pack2(float lo, float hi) {
    unsigned long long r;
    asm("mov.b64 %0, {%1, %2};" : "=l"(r) : "f"(lo), "f"(hi));
    return r;
}
__device__ __forceinline__ void unpack2(unsigned long long v, float& lo, float& hi) {
    asm("mov.b64 {%0, %1}, %2;" : "=f"(lo), "=f"(hi) : "l"(v));
}
__device__ __forceinline__ void fma2(unsigned long long& acc, unsigned long long h, unsigned long long w) {
    asm("fma.rn.f32x2 %0, %1, %2, %0;" : "+l"(acc) : "l"(h), "l"(w));
}
__device__ __forceinline__ void add2(unsigned long long& a, unsigned long long b) {
    asm("add.rn.f32x2 %0, %0, %1;" : "+l"(a) : "l"(b));
}
__device__ __forceinline__ uint32_t f2tf32(float f) {
    uint32_t r;
    asm("cvt.rna.tf32.f32 %0, %1;" : "=r"(r) : "f"(f));
    return r;
}
__device__ __forceinline__ void mma_tf32(float* c, const uint32_t* a, const uint32_t* b) {
    asm("mma.sync.aligned.m16n8k8.row.col.f32.tf32.tf32.f32 "
        "{%0,%1,%2,%3}, {%4,%5,%6,%7}, {%8,%9}, {%0,%1,%2,%3};"
        : "+f"(c[0]), "+f"(c[1]), "+f"(c[2]), "+f"(c[3])
        : "r"(a[0]), "r"(a[1]), "r"(a[2]), "r"(a[3]), "r"(b[0]), "r"(b[1]));
}
__device__ __forceinline__ uint32_t smem_u32(const void* p) {
    uint32_t a;
    asm("{ .reg .u64 t; cvta.to.shared.u64 t, %1; cvt.u32.u64 %0, t; }" : "=r"(a) : "l"(p));
    return a;
}

// ===========================================================================
// Kernel A: xU = X @ U + b   — tf32 tensor cores (unchanged from R4)
// ===========================================================================
__global__ void __launch_bounds__(256) gemm_xu_tc(
    const float* __restrict__ X,
    const float* __restrict__ U,
    const float* __restrict__ bias,
    float* __restrict__ out)
{
    __shared__ float As[128][36];
    __shared__ float Bs[32][132];

    const int tid  = threadIdx.x;
    const int wid  = tid >> 5;
    const int lane = tid & 31;
    const int wm   = (wid & 3) * 32;
    const int wn   = (wid >> 2) * 64;
    const int row0 = blockIdx.y * 128;
    const int col0 = blockIdx.x * 128;

    float acc[2][8][4];
    #pragma unroll
    for (int mt = 0; mt < 2; mt++)
        #pragma unroll
        for (int nt = 0; nt < 8; nt++)
            #pragma unroll
            for (int i = 0; i < 4; i++) acc[mt][nt][i] = 0.0f;

    const int ar = lane >> 2;
    const int ac = lane & 3;
    const int bk = lane & 3;
    const int bn = lane >> 2;

    for (int kb = 0; kb < Dsz; kb += 32) {
        #pragma unroll
        for (int i = 0; i < 4; i++) {
            int lin = tid + i * 256;
            int m = lin >> 3, k = (lin & 7) << 2;
            float4 v = *(const float4*)&X[(size_t)(row0 + m) * Dsz + kb + k];
            v.x = __uint_as_float(f2tf32(v.x));
            v.y = __uint_as_float(f2tf32(v.y));
            v.z = __uint_as_float(f2tf32(v.z));
            v.w = __uint_as_float(f2tf32(v.w));
            *(float4*)&As[m][k] = v;

            int k2 = lin >> 5, n = (lin & 31) << 2;
            float4 u = *(const float4*)&U[(size_t)(kb + k2) * Ksz + col0 + n];
            u.x = __uint_as_float(f2tf32(u.x));
            u.y = __uint_as_float(f2tf32(u.y));
            u.z = __uint_as_float(f2tf32(u.z));
            u.w = __uint_as_float(f2tf32(u.w));
            *(float4*)&Bs[k2][n] = u;
        }
        __syncthreads();

        #pragma unroll
        for (int kc = 0; kc < 4; kc++) {
            const int k0 = kc * 8;
            uint32_t af[2][4];
            #pragma unroll
            for (int mt = 0; mt < 2; mt++) {
                const int mb = wm + mt * 16;
                af[mt][0] = __float_as_uint(As[mb + ar    ][k0 + ac    ]);
                af[mt][1] = __float_as_uint(As[mb + ar + 8][k0 + ac    ]);
                af[mt][2] = __float_as_uint(As[mb + ar    ][k0 + ac + 4]);
                af[mt][3] = __float_as_uint(As[mb + ar + 8][k0 + ac + 4]);
            }
            #pragma unroll
            for (int nt = 0; nt < 8; nt++) {
                uint32_t bf[2];
                const int nb = wn + nt * 8 + bn;
                bf[0] = __float_as_uint(Bs[k0 + bk    ][nb]);
                bf[1] = __float_as_uint(Bs[k0 + bk + 4][nb]);
                mma_tf32(acc[0][nt], af[0], bf);
                mma_tf32(acc[1][nt], af[1], bf);
            }
        }
        __syncthreads();
    }

    #pragma unroll
    for (int nt = 0; nt < 8; nt++) {
        const int cb = col0 + wn + nt * 8 + 2 * (lane & 3);
        float2 bb = *(const float2*)&bias[cb];
        #pragma unroll
        for (int mt = 0; mt < 2; mt++) {
            const int r = row0 + wm + mt * 16 + (lane >> 2);
            float2 o0 = { acc[mt][nt][0] + bb.x, acc[mt][nt][1] + bb.y };
            float2 o1 = { acc[mt][nt][2] + bb.x, acc[mt][nt][3] + bb.y };
            *(float2*)&out[(size_t)r       * Ksz + cb] = o0;
            *(float2*)&out[(size_t)(r + 8) * Ksz + cb] = o1;
        }
    }
}

// ===========================================================================
// Kernel B (R5): recurrence. 64 clusters x 2 CTAs x 512 threads.
// Thread (c, q): c = column within the CTA's 128-column half, q = d-quarter
// (64 d values). W slice (64 floats) in registers -> ~110 regs, 16 warps/SM,
// 4 warps/SMSP for latency hiding. Cross-CTA h exchange via DSMEM stores +
// mbarrier (release/acquire, cluster scope) instead of the ~490-cycle full
// cluster barrier.
// ===========================================================================
#define RROWS 4
#define QW    4          // d-quarters
#define DPT   64         // d per thread
#define KH    128        // columns per CTA

__global__ void __launch_bounds__(512, 1) __cluster_dims__(2, 1, 1)
rnn_rec5_kernel(const float* __restrict__ xU,
                const float* __restrict__ W,
                float* __restrict__ out)
{
    __shared__ float hb[2][Ksz * RROWS];          // 8 KB: [buf][d*4 + r]
    __shared__ ulonglong2 red[QW - 1][KH];        // 6 KB: partials from q=1..3
    __shared__ unsigned long long mbar[2];

    const int tid = threadIdx.x;
    const int c   = tid & (KH - 1);               // 0..127
    const int q   = tid >> 7;                     // 0..3
    uint32_t rank;
    asm("mov.u32 %0, %%cluster_ctarank;" : "=r"(rank));
    const uint32_t peer = rank ^ 1u;
    const int cg = ((int)rank << 7) + c;          // global column 0..255
    const int b0 = (blockIdx.x >> 1) * RROWS;

    // W slice into registers: d in [64q, 64q+64), column cg
    float Wreg[DPT];
    #pragma unroll
    for (int j = 0; j < DPT; j++)
        Wreg[j] = W[(size_t)(q * DPT + j) * Ksz + cg];

    // zero h buffers; init mbarriers (count = 128 remote arrivers per phase)
    for (int i = tid; i < 2 * Ksz * RROWS; i += 512) hb[0][i] = 0.0f;
    if (tid == 0) {
        uint32_t m0 = smem_u32(&mbar[0]);
        uint32_t m1 = smem_u32(&mbar[1]);
        asm volatile("mbarrier.init.shared.b64 [%0], %1;" :: "r"(m0), "r"(KH) : "memory");
        asm volatile("mbarrier.init.shared.b64 [%0], %1;" :: "r"(m1), "r"(KH) : "memory");
    }
    __syncthreads();
    asm volatile("barrier.cluster.arrive.aligned;" ::: "memory");
    asm volatile("barrier.cluster.wait.aligned;"   ::: "memory");

    // addresses
    const uint32_t mbL[2] = { smem_u32(&mbar[0]), smem_u32(&mbar[1]) };
    uint32_t mbP[2];
    asm("mapa.shared::cluster.u32 %0, %1, %2;" : "=r"(mbP[0]) : "r"(mbL[0]), "r"(peer));
    asm("mapa.shared::cluster.u32 %0, %1, %2;" : "=r"(mbP[1]) : "r"(mbL[1]), "r"(peer));
    uint32_t wrL[2], wrP[2];
    #pragma unroll
    for (int p = 0; p < 2; p++) {
        uint32_t a = smem_u32(&hb[p][cg * RROWS]);
        wrL[p] = a;
        asm("mapa.shared::cluster.u32 %0, %1, %2;" : "=r"(wrP[p]) : "r"(a), "r"(peer));
    }

    // xu pointers + first prefetch (q==0 threads consume xu)
    const float* xp0 = xU + ((size_t)(b0 + 0) * Tsz) * Ksz + cg;
    const float* xp1 = xU + ((size_t)(b0 + 1) * Tsz) * Ksz + cg;
    const float* xp2 = xU + ((size_t)(b0 + 2) * Tsz) * Ksz + cg;
    const float* xp3 = xU + ((size_t)(b0 + 3) * Tsz) * Ksz + cg;
    float xu0 = 0.f, xu1 = 0.f, xu2 = 0.f, xu3 = 0.f;
    if (q == 0) { xu0 = xp0[0]; xu1 = xp1[0]; xu2 = xp2[0]; xu3 = xp3[0]; }

    float h0 = 0.f, h1 = 0.f, h2 = 0.f, h3 = 0.f;
    int ph0 = 0, ph1 = 0;

    for (int t = 0; t < Tsz; t++) {
        // wait for peer's h contributions to buffer (t&1), except t==0
        if (t) {
            const int bsel = t & 1;
            uint32_t mb = mbL[bsel];
            int phase = bsel ? ph1 : ph0;
            if (bsel) ph1 ^= 1; else ph0 ^= 1;
            asm volatile(
                "{\n\t"
                ".reg .pred P;\n\t"
                "WL_%=:\n\t"
                "mbarrier.try_wait.parity.acquire.cluster.shared::cta.b64 P, [%0], %1, 0x989680;\n\t"
                "@P bra.uni WD_%=;\n\t"
                "bra.uni WL_%=;\n\t"
                "WD_%=:\n\t"
                "}"
                :: "r"(mb), "r"(phase) : "memory");
        }

        // inner product over this thread's 64 d values
        const double2* hrd = (const double2*)&hb[t & 1][q * (DPT * RROWS)];
        unsigned long long p01 = pack2(0.f, 0.f);
        unsigned long long p23 = p01;
        #pragma unroll
        for (int j = 0; j < DPT; j++) {
            double2 hd = hrd[j];
            unsigned long long w2 = pack2(Wreg[j], Wreg[j]);
            fma2(p01, __double_as_longlong(hd.x), w2);
            fma2(p23, __double_as_longlong(hd.y), w2);
        }

        if (q) red[q - 1][c] = make_ulonglong2(p01, p23);
        __syncthreads();                        // partials visible

        if (q == 0) {
            ulonglong2 r1 = red[0][c];
            ulonglong2 r2 = red[1][c];
            ulonglong2 r3 = red[2][c];
            add2(p01, r1.x); add2(p23, r1.y);
            add2(p01, r2.x); add2(p23, r2.y);
            add2(p01, r3.x); add2(p23, r3.y);
            add2(p01, pack2(xu0, xu1));
            add2(p23, pack2(xu2, xu3));
            // prefetch next xu
            {
                int tn = (t + 1 < Tsz) ? t + 1 : t;
                size_t off = (size_t)tn * Ksz;
                xu0 = xp0[off]; xu1 = xp1[off]; xu2 = xp2[off]; xu3 = xp3[off];
            }
            float s0, s1, s2, s3;
            unpack2(p01, s0, s1);
            unpack2(p23, s2, s3);
            h0 = tanhf(s0); h1 = tanhf(s1); h2 = tanhf(s2); h3 = tanhf(s3);

            if (t + 1 < Tsz) {
                const int p = (t + 1) & 1;
                asm volatile("st.shared.v4.f32 [%0], {%1, %2, %3, %4};"
                             :: "r"(wrL[p]), "f"(h0), "f"(h1), "f"(h2), "f"(h3) : "memory");
                asm volatile("st.shared::cluster.v4.f32 [%0], {%1, %2, %3, %4};"
                             :: "r"(wrP[p]), "f"(h0), "f"(h1), "f"(h2), "f"(h3) : "memory");
                // release-arrive on peer's barrier for buffer p (orders the store)
                asm volatile("mbarrier.arrive.release.cluster.shared::cluster.b64 _, [%0];"
                             :: "r"(mbP[p]) : "memory");
            }
        }
        __syncthreads();                        // local h writes visible; red reusable
    }

    if (q == 0) {
        out[(size_t)(b0 + 0) * Ksz + cg] = h0;
        out[(size_t)(b0 + 1) * Ksz + cg] = h1;
        out[(size_t)(b0 + 2) * Ksz + cg] = h2;
        out[(size_t)(b0 + 3) * Ksz + cg] = h3;
    }
}

// ===========================================================================
// Launch
// ===========================================================================
extern "C" void kernel_launch(void* const* d_in, const int* in_sizes, int n_in,
                              void* d_out, int out_size)
{
    const float* x    = (const float*)d_in[0];   // [256, 512, 256]
    const float* U    = (const float*)d_in[1];   // [256, 256]
    const float* W    = (const float*)d_in[2];   // [256, 256]
    const float* bias = (const float*)d_in[3];   // [256]
    float* out        = (float*)d_out;           // [256, 1, 256]

    float* xU;
    cudaGetSymbolAddress((void**)&xU, g_xU);

    dim3 gridA(Ksz / 128, (Bsz * Tsz) / 128);    // (2, 1024)
    gemm_xu_tc<<<gridA, 256>>>(x, U, bias, xU);

    rnn_rec5_kernel<<<(Bsz / RROWS) * 2, 512>>>(xU, W, out);
}